// round 9
// baseline (speedup 1.0000x reference)
#include <cuda_runtime.h>
#include <cuda_bf16.h>

// VoConstruction: out[b] = Re( O @ (Umat d Umat^H) ), O = [[0,1],[1,0]].
// Closed form (delta factor cancels; only real parts survive in the output):
//   c = cos(u1), s = sin(u1), lam1 = 2*x1, lam2 = 2*x2*(1-|x1|)
//   ReH00 = lam1 c^2 + lam2 s^2, ReH11 = lam1 s^2 + lam2 c^2
//   ReH01 = ReH10 = c s (lam2 - lam1) cos(2 u0)
// out[b] (float32 [2,2]) = (ReH10, ReH11, ReH00, ReH01) -> one float4.
//
// Vectorized: 4 elements/thread. U rows 4t..4t+3 = 12 contiguous floats =
// 3 aligned float4 loads; x1/x2 one float4 each; 4 float4 stores.

__global__ __launch_bounds__(256)
void vo_real4_kernel(const float4* __restrict__ U4,   // quads*3 float4
                     const float4* __restrict__ X1,   // quads float4
                     const float4* __restrict__ X2,   // quads float4
                     float4* __restrict__ out,        // 4 float4 per thread
                     int quads)
{
    int t = blockIdx.x * blockDim.x + threadIdx.x;
    if (t >= quads) return;

    const float4 a = U4[3 * t + 0];
    const float4 b = U4[3 * t + 1];
    const float4 c = U4[3 * t + 2];
    const float4 x1v = X1[t];
    const float4 x2v = X2[t];

    float u0[4] = { a.x, a.w, b.z, c.y };
    float th[4] = { a.y, b.x, b.w, c.z };
    float l1[4] = { x1v.x, x1v.y, x1v.z, x1v.w };
    float l2[4] = { x2v.x, x2v.y, x2v.z, x2v.w };

    float4* o = out + (size_t)4 * t;

#pragma unroll
    for (int j = 0; j < 4; ++j) {
        float s, ct;
        __sincosf(th[j], &s, &ct);
        float c2 = __cosf(2.0f * u0[j]);

        float lam1 = 2.0f * l1[j];
        float lam2 = 2.0f * l2[j] * (1.0f - fabsf(l1[j]));

        float cc = ct * ct;
        float ss = s * s;
        float h00 = fmaf(lam1, cc, lam2 * ss);
        float h11 = fmaf(lam1, ss, lam2 * cc);
        float wc  = ct * s * (lam2 - lam1) * c2;

        o[j] = make_float4(wc, h11, h00, wc);   // [ReH10, ReH11, ReH00, ReH01]
    }
}

// Scalar tail for B % 4 != 0 (element indices [start, B)).
__global__ __launch_bounds__(64)
void vo_real_tail_kernel(const float* __restrict__ U,
                         const float* __restrict__ X1,
                         const float* __restrict__ X2,
                         float4* __restrict__ out,
                         int start, int B)
{
    int i = start + blockIdx.x * blockDim.x + threadIdx.x;
    if (i >= B) return;

    float u0 = U[3 * i + 0];
    float th = U[3 * i + 1];
    float l1 = X1[i];
    float l2 = X2[i];

    float s, ct;
    __sincosf(th, &s, &ct);
    float c2 = __cosf(2.0f * u0);

    float lam1 = 2.0f * l1;
    float lam2 = 2.0f * l2 * (1.0f - fabsf(l1));

    float cc = ct * ct;
    float ss = s * s;
    float h00 = fmaf(lam1, cc, lam2 * ss);
    float h11 = fmaf(lam1, ss, lam2 * cc);
    float wc  = ct * s * (lam2 - lam1) * c2;

    out[i] = make_float4(wc, h11, h00, wc);
}

extern "C" void kernel_launch(void* const* d_in, const int* in_sizes, int n_in,
                              void* d_out, int out_size)
{
    if (n_in < 3) return;

    // U = largest input; x1, x2 = the two largest remaining (original order).
    int iU = 0;
    for (int i = 1; i < n_in; ++i)
        if (in_sizes[i] > in_sizes[iU]) iU = i;

    int iA = -1, iB = -1;
    for (int i = 0; i < n_in; ++i) {
        if (i == iU) continue;
        if (iA < 0) { iA = i; continue; }
        if (iB < 0) { iB = i; continue; }
        int iMin = (in_sizes[iA] <= in_sizes[iB]) ? iA : iB;
        if (in_sizes[i] > in_sizes[iMin]) {
            if (iMin == iA) iA = iB;
            iB = i;
        }
    }
    if (iA < 0 || iB < 0) return;
    int iX1 = (iA < iB) ? iA : iB;
    int iX2 = (iA < iB) ? iB : iA;

    long long B = in_sizes[iX1];
    if ((long long)in_sizes[iX2] < B) B = in_sizes[iX2];
    if ((long long)in_sizes[iU] / 3 < B) B = in_sizes[iU] / 3;
    if ((long long)out_size / 4 < B) B = out_size / 4;   // float32 [B,2,2]
    if (B <= 0) return;

    const float* pU  = (const float*)d_in[iU];
    const float* pX1 = (const float*)d_in[iX1];
    const float* pX2 = (const float*)d_in[iX2];

    int Bi    = (int)B;
    int quads = Bi / 4;
    int rem   = Bi - 4 * quads;

    if (quads > 0) {
        dim3 block(256);
        dim3 grid((quads + 255) / 256);
        vo_real4_kernel<<<grid, block>>>((const float4*)pU,
                                         (const float4*)pX1,
                                         (const float4*)pX2,
                                         (float4*)d_out, quads);
    }
    if (rem > 0) {
        vo_real_tail_kernel<<<1, 64>>>(pU, pX1, pX2, (float4*)d_out,
                                       4 * quads, Bi);
    }
}

// round 11
// speedup vs baseline: 1.1751x; 1.1751x over previous
#include <cuda_runtime.h>
#include <cuda_bf16.h>

// VoConstruction: out[b] = Re( O @ (Umat d Umat^H) ), O = [[0,1],[1,0]].
// Closed form (delta cancels; only real parts survive in the f32 output):
//   c = cos(u1), s = sin(u1), lam1 = 2*x1, lam2 = 2*x2*(1-|x1|)
//   ReH00 = lam1 c^2 + lam2 s^2, ReH11 = lam1 s^2 + lam2 c^2
//   ReH01 = ReH10 = c s (lam2 - lam1) cos(2 u0)
// out[b] = (ReH10, ReH11, ReH00, ReH01) -> one float4.
//
// Smem-staged: block handles 1024 elements. U slab (12 KB) loaded as 768
// consecutive float4 (perfect coalescing), then read back scalar at offset
// 3k (gcd(3,32)=1 -> conflict-free). x1/x2 scalar coalesced; stores float4
// consecutive across the warp. Every global transaction is fully utilized.

static constexpr int ELEMS_PER_BLOCK = 1024;   // 256 threads * 4 elems

__global__ __launch_bounds__(256)
void vo_smem_kernel(const float4* __restrict__ U4,   // [3B/4] float4
                    const float* __restrict__ X1,
                    const float* __restrict__ X2,
                    float4* __restrict__ out)        // 1 float4 per element
{
    __shared__ float sU[3 * ELEMS_PER_BLOCK];        // 12 KB

    int lt   = threadIdx.x;
    int base = blockIdx.x * ELEMS_PER_BLOCK;         // B < 2^28 -> fits int

    // U floats for this block: [3*base, 3*base+3072) = 768 float4, coalesced.
    int uf4 = (3 * base) >> 2;                       // base % 4 == 0 always
#pragma unroll
    for (int j = 0; j < 3; ++j) {
        ((float4*)sU)[lt + 256 * j] = U4[uf4 + lt + 256 * j];
    }
    __syncthreads();

#pragma unroll
    for (int j = 0; j < 4; ++j) {
        int k = lt + 256 * j;                        // local element
        int i = base + k;                            // global element

        float u0 = sU[3 * k + 0];
        float th = sU[3 * k + 1];
        float l1 = X1[i];
        float l2 = X2[i];

        float s, ct;
        __sincosf(th, &s, &ct);
        float c2 = __cosf(2.0f * u0);

        float lam1 = 2.0f * l1;
        float lam2 = 2.0f * l2 * (1.0f - fabsf(l1));

        float cc = ct * ct;
        float ss = s * s;
        float h00 = fmaf(lam1, cc, lam2 * ss);
        float h11 = fmaf(lam1, ss, lam2 * cc);
        float wc  = ct * s * (lam2 - lam1) * c2;

        out[i] = make_float4(wc, h11, h00, wc);      // [ReH10,ReH11,ReH00,ReH01]
    }
}

// Scalar kernel for the tail [start, B) — proven R8 path.
__global__ __launch_bounds__(256)
void vo_real_tail_kernel(const float* __restrict__ U,
                         const float* __restrict__ X1,
                         const float* __restrict__ X2,
                         float4* __restrict__ out,
                         int start, int B)
{
    int i = start + blockIdx.x * blockDim.x + threadIdx.x;
    if (i >= B) return;

    float u0 = U[3 * i + 0];
    float th = U[3 * i + 1];
    float l1 = X1[i];
    float l2 = X2[i];

    float s, ct;
    __sincosf(th, &s, &ct);
    float c2 = __cosf(2.0f * u0);

    float lam1 = 2.0f * l1;
    float lam2 = 2.0f * l2 * (1.0f - fabsf(l1));

    float cc = ct * ct;
    float ss = s * s;
    float h00 = fmaf(lam1, cc, lam2 * ss);
    float h11 = fmaf(lam1, ss, lam2 * cc);
    float wc  = ct * s * (lam2 - lam1) * c2;

    out[i] = make_float4(wc, h11, h00, wc);
}

extern "C" void kernel_launch(void* const* d_in, const int* in_sizes, int n_in,
                              void* d_out, int out_size)
{
    if (n_in < 3) return;

    // U = largest input; x1, x2 = the two largest remaining (original order).
    int iU = 0;
    for (int i = 1; i < n_in; ++i)
        if (in_sizes[i] > in_sizes[iU]) iU = i;

    int iA = -1, iB = -1;
    for (int i = 0; i < n_in; ++i) {
        if (i == iU) continue;
        if (iA < 0) { iA = i; continue; }
        if (iB < 0) { iB = i; continue; }
        int iMin = (in_sizes[iA] <= in_sizes[iB]) ? iA : iB;
        if (in_sizes[i] > in_sizes[iMin]) {
            if (iMin == iA) iA = iB;
            iB = i;
        }
    }
    if (iA < 0 || iB < 0) return;
    int iX1 = (iA < iB) ? iA : iB;
    int iX2 = (iA < iB) ? iB : iA;

    long long B = in_sizes[iX1];
    if ((long long)in_sizes[iX2] < B) B = in_sizes[iX2];
    if ((long long)in_sizes[iU] / 3 < B) B = in_sizes[iU] / 3;
    if ((long long)out_size / 4 < B) B = out_size / 4;   // float32 [B,2,2]
    if (B <= 0) return;

    const float* pU  = (const float*)d_in[iU];
    const float* pX1 = (const float*)d_in[iX1];
    const float* pX2 = (const float*)d_in[iX2];

    int Bi     = (int)B;
    int nfull  = Bi / ELEMS_PER_BLOCK;               // full 1024-elem blocks
    int start  = nfull * ELEMS_PER_BLOCK;
    int rem    = Bi - start;

    if (nfull > 0) {
        vo_smem_kernel<<<nfull, 256>>>((const float4*)pU, pX1, pX2,
                                       (float4*)d_out);
    }
    if (rem > 0) {
        int blocks = (rem + 255) / 256;
        vo_real_tail_kernel<<<blocks, 256>>>(pU, pX1, pX2, (float4*)d_out,
                                             start, Bi);
    }
}

// round 12
// speedup vs baseline: 1.2189x; 1.0373x over previous
#include <cuda_runtime.h>
#include <cuda_bf16.h>

// VoConstruction: out[b] = Re( O @ (Umat d Umat^H) ), O = [[0,1],[1,0]].
// Closed form (delta cancels; only real parts survive in the f32 output):
//   c = cos(u1), s = sin(u1), lam1 = 2*x1, lam2 = 2*x2*(1-|x1|)
//   ReH00 = lam1 c^2 + lam2 s^2, ReH11 = lam1 s^2 + lam2 c^2
//   ReH01 = ReH10 = c s (lam2 - lam1) cos(2 u0)
// out[b] = (ReH10, ReH11, ReH00, ReH01) -> one float4.
//
// Smem-staged, 2048 elems/block (8/thread): U slab (24 KB) loaded as 1536
// consecutive float4 via __ldcs (read-once, keep L2 for x1/x2), conflict-free
// smem readback (stride 3, gcd(3,32)=1), coalesced x1/x2, __stwt float4
// stores (streaming write-through; output never re-read).

static constexpr int ELEMS_PER_BLOCK = 2048;   // 256 threads * 8 elems

__global__ __launch_bounds__(256)
void vo_smem_kernel(const float4* __restrict__ U4,   // [3B/4] float4
                    const float* __restrict__ X1,
                    const float* __restrict__ X2,
                    float4* __restrict__ out)        // 1 float4 per element
{
    __shared__ float sU[3 * ELEMS_PER_BLOCK];        // 24 KB

    int lt   = threadIdx.x;
    int base = blockIdx.x * ELEMS_PER_BLOCK;         // fits int (B < 2^28)

    // U floats for this block: [3*base, 3*base+6144) = 1536 float4, coalesced.
    int uf4 = (3 * base) >> 2;                       // base % 4 == 0 always
#pragma unroll
    for (int j = 0; j < 6; ++j) {
        ((float4*)sU)[lt + 256 * j] = __ldcs(&U4[uf4 + lt + 256 * j]);
    }
    __syncthreads();

#pragma unroll
    for (int j = 0; j < 8; ++j) {
        int k = lt + 256 * j;                        // local element
        int i = base + k;                            // global element

        float u0 = sU[3 * k + 0];
        float th = sU[3 * k + 1];
        float l1 = X1[i];
        float l2 = X2[i];

        float s, ct;
        __sincosf(th, &s, &ct);
        float c2 = __cosf(2.0f * u0);

        float lam1 = 2.0f * l1;
        float lam2 = 2.0f * l2 * (1.0f - fabsf(l1));

        float cc = ct * ct;
        float ss = s * s;
        float h00 = fmaf(lam1, cc, lam2 * ss);
        float h11 = fmaf(lam1, ss, lam2 * cc);
        float wc  = ct * s * (lam2 - lam1) * c2;

        __stwt(&out[i], make_float4(wc, h11, h00, wc));  // [ReH10,ReH11,ReH00,ReH01]
    }
}

// Scalar kernel for the tail [start, B) — proven R8 path.
__global__ __launch_bounds__(256)
void vo_real_tail_kernel(const float* __restrict__ U,
                         const float* __restrict__ X1,
                         const float* __restrict__ X2,
                         float4* __restrict__ out,
                         int start, int B)
{
    int i = start + blockIdx.x * blockDim.x + threadIdx.x;
    if (i >= B) return;

    float u0 = U[3 * i + 0];
    float th = U[3 * i + 1];
    float l1 = X1[i];
    float l2 = X2[i];

    float s, ct;
    __sincosf(th, &s, &ct);
    float c2 = __cosf(2.0f * u0);

    float lam1 = 2.0f * l1;
    float lam2 = 2.0f * l2 * (1.0f - fabsf(l1));

    float cc = ct * ct;
    float ss = s * s;
    float h00 = fmaf(lam1, cc, lam2 * ss);
    float h11 = fmaf(lam1, ss, lam2 * cc);
    float wc  = ct * s * (lam2 - lam1) * c2;

    out[i] = make_float4(wc, h11, h00, wc);
}

extern "C" void kernel_launch(void* const* d_in, const int* in_sizes, int n_in,
                              void* d_out, int out_size)
{
    if (n_in < 3) return;

    // U = largest input; x1, x2 = the two largest remaining (original order).
    int iU = 0;
    for (int i = 1; i < n_in; ++i)
        if (in_sizes[i] > in_sizes[iU]) iU = i;

    int iA = -1, iB = -1;
    for (int i = 0; i < n_in; ++i) {
        if (i == iU) continue;
        if (iA < 0) { iA = i; continue; }
        if (iB < 0) { iB = i; continue; }
        int iMin = (in_sizes[iA] <= in_sizes[iB]) ? iA : iB;
        if (in_sizes[i] > in_sizes[iMin]) {
            if (iMin == iA) iA = iB;
            iB = i;
        }
    }
    if (iA < 0 || iB < 0) return;
    int iX1 = (iA < iB) ? iA : iB;
    int iX2 = (iA < iB) ? iB : iA;

    long long B = in_sizes[iX1];
    if ((long long)in_sizes[iX2] < B) B = in_sizes[iX2];
    if ((long long)in_sizes[iU] / 3 < B) B = in_sizes[iU] / 3;
    if ((long long)out_size / 4 < B) B = out_size / 4;   // float32 [B,2,2]
    if (B <= 0) return;

    const float* pU  = (const float*)d_in[iU];
    const float* pX1 = (const float*)d_in[iX1];
    const float* pX2 = (const float*)d_in[iX2];

    int Bi     = (int)B;
    int nfull  = Bi / ELEMS_PER_BLOCK;               // full 2048-elem blocks
    int start  = nfull * ELEMS_PER_BLOCK;
    int rem    = Bi - start;

    if (nfull > 0) {
        vo_smem_kernel<<<nfull, 256>>>((const float4*)pU, pX1, pX2,
                                       (float4*)d_out);
    }
    if (rem > 0) {
        int blocks = (rem + 255) / 256;
        vo_real_tail_kernel<<<blocks, 256>>>(pU, pX1, pX2, (float4*)d_out,
                                             start, Bi);
    }
}